// round 3
// baseline (speedup 1.0000x reference)
#include <cuda_runtime.h>
#include <cuda_bf16.h>
#include <cstdint>
#include <math.h>

// ---------------- problem constants ----------------
#define D_MODEL   1024
#define NUM_TILES 64
#define TPC       8
#define NUM_CL    8
#define COMP_H    256
#define GRIDW     16
#define EPS_LN    1e-5f

// GEMM config
#define NCOL      328          // 256 hidden + 8 cluster + 64 tile
#define NCOL_PAD  352          // 44 n8-tiles
#define M_BLK     64
#define KC        64           // k-chunk
#define NCHUNK    (D_MODEL / KC)   // 16
#define ASTRIDE   (KC + 8)     // 72, conflict-free padding
#define CSTRIDE   (NCOL_PAD + 4)   // 356

// Wcat, chunk-major for coalesced per-chunk fill: [chunk][row n][k within chunk]
__device__ __nv_bfloat16 g_Wcat[NCHUNK][NCOL_PAD][KC];

// ---------------- prep kernel: build ternary sigs + cluster sigs + bf16 W1 ----
__global__ void prep_kernel(const float* __restrict__ raw,
                            const float* __restrict__ w1) {
    int idx = blockIdx.x * blockDim.x + threadIdx.x;
    if (idx >= NCOL_PAD * D_MODEL) return;
    int n = idx / D_MODEL;
    int k = idx % D_MODEL;
    float val;
    if (n < COMP_H) {
        val = w1[k * COMP_H + n];                 // compress_w1 [D][H]
    } else if (n < COMP_H + NUM_CL) {
        int c = n - COMP_H;
        float s = 0.f;
        #pragma unroll
        for (int j = 0; j < TPC; ++j) {
            float rv = raw[(c * TPC + j) * D_MODEL + k];
            s += (rv > 0.3f) ? 1.f : ((rv < -0.3f) ? -1.f : 0.f);
        }
        val = (s > 0.f) ? 1.f : ((s < 0.f) ? -1.f : 0.f);
    } else if (n < COMP_H + NUM_CL + NUM_TILES) {
        float rv = raw[(n - COMP_H - NUM_CL) * D_MODEL + k];
        val = (rv > 0.3f) ? 1.f : ((rv < -0.3f) ? -1.f : 0.f);
    } else {
        val = 0.f;
    }
    g_Wcat[k >> 6][n][k & 63] = __float2bfloat16(val);
}

// ---------------- helpers ----------------
__device__ __forceinline__ float gelu_exact(float v) {
    return 0.5f * v * (1.0f + erff(v * 0.7071067811865476f));
}

__device__ __forceinline__ void mma16816(float c[4], uint32_t a0, uint32_t a1,
                                         uint32_t a2, uint32_t a3,
                                         uint32_t b0, uint32_t b1) {
    asm volatile(
        "mma.sync.aligned.m16n8k16.row.col.f32.bf16.bf16.f32 "
        "{%0,%1,%2,%3}, {%4,%5,%6,%7}, {%8,%9}, {%0,%1,%2,%3};\n"
        : "+f"(c[0]), "+f"(c[1]), "+f"(c[2]), "+f"(c[3])
        : "r"(a0), "r"(a1), "r"(a2), "r"(a3), "r"(b0), "r"(b1));
}

// argmax over warp, first-index tie-break (all lanes converge)
__device__ __forceinline__ void warp_argmax(float& v, int& i) {
    #pragma unroll
    for (int o = 16; o; o >>= 1) {
        float ov = __shfl_xor_sync(0xffffffffu, v, o);
        int   oi = __shfl_xor_sync(0xffffffffu, i, o);
        if (ov > v || (ov == v && oi < i)) { v = ov; i = oi; }
    }
}

__device__ __forceinline__ float warp_sum(float v) {
    #pragma unroll
    for (int o = 16; o; o >>= 1) v += __shfl_xor_sync(0xffffffffu, v, o);
    return v;
}

// ---------------- main fused kernel ----------------
// smem layout:
//   bytes [0, 91136): union { GEMM stage {A[64][72], B[352][72]} bf16 | C[64][356] f32 }
//   bytes [91136, 94208): param cache b1c[256], w2c0[256], w2c1[256]
#define SMEM_C_BYTES (M_BLK * CSTRIDE * 4)
#define SMEM_TOTAL   (SMEM_C_BYTES + 3 * COMP_H * 4)

__global__ void __launch_bounds__(256)
fused_kernel(const float* __restrict__ X,
             const float* __restrict__ cb1,
             const float* __restrict__ cw2,
             const float* __restrict__ cb2,
             const float* __restrict__ sw1,
             const float* __restrict__ sb1,
             const float* __restrict__ sw2,
             const float* __restrict__ sb2,
             const float* __restrict__ dirs,
             const float* __restrict__ gamma,
             const float* __restrict__ beta,
             const float* __restrict__ oscale_p,
             float* __restrict__ out) {
    extern __shared__ char sm[];
    float*         Csm = (float*)sm;
    __nv_bfloat16* Asm = (__nv_bfloat16*)sm;
    __nv_bfloat16* Bsm = Asm + M_BLK * ASTRIDE;
    float* b1c  = (float*)(sm + SMEM_C_BYTES);
    float* w2c0 = b1c + COMP_H;
    float* w2c1 = w2c0 + COMP_H;

    const int tid  = threadIdx.x;
    const int lane = tid & 31;
    const int wid  = tid >> 5;
    const int mw   = wid >> 1;      // 0..3  (m16 subtile)
    const int nw   = wid & 1;       // 0..1  (22 n8-tiles each)
    const int r0   = blockIdx.x * M_BLK;

    // param cache
    if (tid < COMP_H) {
        b1c[tid]  = cb1[tid];
        w2c0[tid] = cw2[tid * 2 + 0];
        w2c1[tid] = cw2[tid * 2 + 1];
    }
    const float oscale = oscale_p[0];
    const float b2_0 = cb2[0];
    const float b2_1 = cb2[1];

    float acc[22][4];
    #pragma unroll
    for (int t = 0; t < 22; ++t)
        #pragma unroll
        for (int j = 0; j < 4; ++j) acc[t][j] = 0.f;

    // -------- GEMM mainloop --------
    for (int kc = 0; kc < NCHUNK; ++kc) {
        // A fill: 64 rows x 64 k of X (fp32 -> bf16)
        #pragma unroll
        for (int rep = 0; rep < 4; ++rep) {
            int s   = tid + rep * 256;        // 0..1023 float4 slots
            int row = s >> 4;                 // 16 float4 per row
            int c4  = s & 15;
            float4 v = ((const float4*)X)[(size_t)(r0 + row) * (D_MODEL / 4) + kc * (KC / 4) + c4];
            __nv_bfloat162 p0 = __floats2bfloat162_rn(v.x, v.y);
            __nv_bfloat162 p1 = __floats2bfloat162_rn(v.z, v.w);
            *(__nv_bfloat162*)&Asm[row * ASTRIDE + c4 * 4]     = p0;
            *(__nv_bfloat162*)&Asm[row * ASTRIDE + c4 * 4 + 2] = p1;
        }
        // B fill: 352 rows x 64 k bf16 (contiguous chunk block)
        {
            const uint4* src = (const uint4*)&g_Wcat[kc][0][0];   // 2816 uint4
            #pragma unroll
            for (int rep = 0; rep < 11; ++rep) {
                int s = tid + rep * 256;
                uint4 v = src[s];
                int row = s >> 3;             // 8 uint4 per row (64 bf16)
                int q   = s & 7;
                *(uint4*)&Bsm[row * ASTRIDE + q * 8] = v;
            }
        }
        __syncthreads();

        #pragma unroll
        for (int ks = 0; ks < 4; ++ks) {
            const int ar = mw * 16 + (lane >> 2);
            const int ac = ks * 16 + (lane & 3) * 2;
            uint32_t a0 = *(const uint32_t*)&Asm[ar * ASTRIDE + ac];
            uint32_t a1 = *(const uint32_t*)&Asm[(ar + 8) * ASTRIDE + ac];
            uint32_t a2 = *(const uint32_t*)&Asm[ar * ASTRIDE + ac + 8];
            uint32_t a3 = *(const uint32_t*)&Asm[(ar + 8) * ASTRIDE + ac + 8];
            #pragma unroll
            for (int nt = 0; nt < 22; ++nt) {
                int br = (nw * 22 + nt) * 8 + (lane >> 2);
                uint32_t b0 = *(const uint32_t*)&Bsm[br * ASTRIDE + ac];
                uint32_t b1 = *(const uint32_t*)&Bsm[br * ASTRIDE + ac + 8];
                mma16816(acc[nt], a0, a1, a2, a3, b0, b1);
            }
        }
        __syncthreads();
    }

    // -------- dump C to smem --------
    #pragma unroll
    for (int nt = 0; nt < 22; ++nt) {
        int nb = (nw * 22 + nt) * 8;
        int cr = mw * 16 + (lane >> 2);
        int cc = nb + (lane & 3) * 2;
        *(float2*)&Csm[cr * CSTRIDE + cc]       = make_float2(acc[nt][0], acc[nt][1]);
        *(float2*)&Csm[(cr + 8) * CSTRIDE + cc] = make_float2(acc[nt][2], acc[nt][3]);
    }
    __syncthreads();

    // -------- epilogue: one warp per token, 8 tokens per warp --------
    for (int it = 0; it < 8; ++it) {
        const int m = wid * 8 + it;
        const int r = r0 + m;
        const float* crow = Csm + m * CSTRIDE;

        // compress head: gelu(h) @ W2 -> tanh
        float s0 = 0.f, s1 = 0.f;
        #pragma unroll
        for (int jj = 0; jj < 8; ++jj) {
            int j = lane + jj * 32;
            float h = gelu_exact(crow[j] + b1c[j]);
            s0 += h * w2c0[j];
            s1 += h * w2c1[j];
        }
        s0 = warp_sum(s0);
        s1 = warp_sum(s1);
        float comp0 = tanhf(s0 + b2_0);
        float comp1 = tanhf(s1 + b2_1);

        // routing (calibration is monotone -> argmax on raw scores)
        float cv = -INFINITY; int ci = 1 << 20;
        if (lane < NUM_CL) { cv = crow[COMP_H + lane]; ci = lane; }
        warp_argmax(cv, ci);
        float tv = -INFINITY; int tl = 1 << 20;
        if (lane < TPC) { tv = crow[COMP_H + NUM_CL + ci * TPC + lane]; tl = lane; }
        warp_argmax(tv, tl);
        const int tile = ci * TPC + tl;

        // tiny spline MLP for magnitude
        float contrib = 0.f;
        if (lane < GRIDW) {
            int g = lane;
            float hw = comp0 * sw1[tile * 32 + g] + comp1 * sw1[tile * 32 + 16 + g]
                       + sb1[tile * 16 + g];
            hw = fmaxf(hw, 0.f);
            contrib = hw * sw2[tile * 16 + g];
        }
        float mag = warp_sum(contrib) + sb2[tile];
        const float factor = mag * oscale;

        // residual + layernorm
        const float* xr = X + (size_t)r * D_MODEL;
        const float* dr = dirs + (size_t)tile * D_MODEL;
        float f[32];
        float sum = 0.f, sumsq = 0.f;
        #pragma unroll
        for (int ii = 0; ii < 32; ++ii) {
            int i = lane + ii * 32;
            float y = xr[i] + factor * dr[i];
            f[ii] = y;
            sum += y;
            sumsq += y * y;
        }
        sum   = warp_sum(sum);
        sumsq = warp_sum(sumsq);
        const float mu   = sum * (1.f / D_MODEL);
        const float var  = sumsq * (1.f / D_MODEL) - mu * mu;
        const float rstd = rsqrtf(var + EPS_LN);
        float* orow = out + (size_t)r * D_MODEL;
        #pragma unroll
        for (int ii = 0; ii < 32; ++ii) {
            int i = lane + ii * 32;
            orow[i] = (f[ii] - mu) * rstd * gamma[i] + beta[i];
        }
    }
}

// ---------------- launch ----------------
extern "C" void kernel_launch(void* const* d_in, const int* in_sizes, int n_in,
                              void* d_out, int out_size) {
    const float* x      = (const float*)d_in[0];
    const float* sraw   = (const float*)d_in[1];
    // d_in[2] knot_values, d_in[3] temperature: unused (calibration monotone)
    const float* cw1    = (const float*)d_in[4];
    const float* cb1    = (const float*)d_in[5];
    const float* cw2    = (const float*)d_in[6];
    const float* cb2    = (const float*)d_in[7];
    const float* sw1    = (const float*)d_in[8];
    const float* sb1    = (const float*)d_in[9];
    const float* sw2    = (const float*)d_in[10];
    const float* sb2    = (const float*)d_in[11];
    const float* dirs   = (const float*)d_in[12];
    const float* gamma  = (const float*)d_in[13];
    const float* beta   = (const float*)d_in[14];
    const float* oscale = (const float*)d_in[15];
    float* out = (float*)d_out;

    const int N = in_sizes[0] / D_MODEL;        // 16384
    const int nblocks = N / M_BLK;              // 256

    cudaFuncSetAttribute(fused_kernel,
                         cudaFuncAttributeMaxDynamicSharedMemorySize, SMEM_TOTAL);

    prep_kernel<<<(NCOL_PAD * D_MODEL + 255) / 256, 256>>>(sraw, cw1);
    fused_kernel<<<nblocks, 256, SMEM_TOTAL>>>(
        x, cb1, cw2, cb2, sw1, sb1, sw2, sb2, dirs, gamma, beta, oscale, out);
}

// round 4
// speedup vs baseline: 1.0721x; 1.0721x over previous
#include <cuda_runtime.h>
#include <cuda_bf16.h>
#include <cstdint>
#include <math.h>

// ---------------- problem constants ----------------
#define D_MODEL   1024
#define NUM_TILES 64
#define TPC       8
#define NUM_CL    8
#define COMP_H    256
#define GRIDW     16
#define EPS_LN    1e-5f

// GEMM config
#define NCOL_PAD  352              // 44 n8-tiles (256 hidden + 8 cluster + 64 tile + pad)
#define M_BLK     64
#define KC        64
#define NCHUNK    (D_MODEL / KC)   // 16
#define ASTRIDE   (KC + 8)         // 72, conflict-free
#define CSTRIDE   (NCOL_PAD + 4)   // 356
#define NTHREADS  512
#define NT_PER    11               // n8-tiles per warp (4 n-warps)

#define A_BYTES      (M_BLK * ASTRIDE * 2)       // 9216
#define B_BYTES      (NCOL_PAD * ASTRIDE * 2)    // 50688
#define STAGE_BYTES  (2 * A_BYTES + B_BYTES)     // 69120 (A_hi, A_lo, B)
#define PARAM_OFF    (2 * STAGE_BYTES)           // 138240
#define SMEM_TOTAL   (PARAM_OFF + 3 * COMP_H * 4)

// Wcat, chunk-major: [chunk][row n][k within chunk]
__device__ __nv_bfloat16 g_Wcat[NCHUNK][NCOL_PAD][KC];

// ---------------- prep: ternary sigs + cluster sigs + bf16 W1 ----------------
__global__ void prep_kernel(const float* __restrict__ raw,
                            const float* __restrict__ w1) {
    int idx = blockIdx.x * blockDim.x + threadIdx.x;
    if (idx >= NCOL_PAD * D_MODEL) return;
    int n = idx / D_MODEL;
    int k = idx % D_MODEL;
    float val;
    if (n < COMP_H) {
        val = w1[k * COMP_H + n];
    } else if (n < COMP_H + NUM_CL) {
        int c = n - COMP_H;
        float s = 0.f;
        #pragma unroll
        for (int j = 0; j < TPC; ++j) {
            float rv = raw[(c * TPC + j) * D_MODEL + k];
            s += (rv > 0.3f) ? 1.f : ((rv < -0.3f) ? -1.f : 0.f);
        }
        val = (s > 0.f) ? 1.f : ((s < 0.f) ? -1.f : 0.f);
    } else if (n < COMP_H + NUM_CL + NUM_TILES) {
        float rv = raw[(n - COMP_H - NUM_CL) * D_MODEL + k];
        val = (rv > 0.3f) ? 1.f : ((rv < -0.3f) ? -1.f : 0.f);
    } else {
        val = 0.f;
    }
    g_Wcat[k >> 6][n][k & 63] = __float2bfloat16(val);
}

// ---------------- helpers ----------------
__device__ __forceinline__ float gelu_exact(float v) {
    return 0.5f * v * (1.0f + erff(v * 0.7071067811865476f));
}

__device__ __forceinline__ void mma16816(float c[4], uint32_t a0, uint32_t a1,
                                         uint32_t a2, uint32_t a3,
                                         uint32_t b0, uint32_t b1) {
    asm volatile(
        "mma.sync.aligned.m16n8k16.row.col.f32.bf16.bf16.f32 "
        "{%0,%1,%2,%3}, {%4,%5,%6,%7}, {%8,%9}, {%0,%1,%2,%3};\n"
        : "+f"(c[0]), "+f"(c[1]), "+f"(c[2]), "+f"(c[3])
        : "r"(a0), "r"(a1), "r"(a2), "r"(a3), "r"(b0), "r"(b1));
}

__device__ __forceinline__ void cp16(uint32_t dst, const void* src) {
    asm volatile("cp.async.ca.shared.global [%0], [%1], 16;\n" :: "r"(dst), "l"(src));
}

__device__ __forceinline__ void warp_argmax(float& v, int& i) {
    #pragma unroll
    for (int o = 16; o; o >>= 1) {
        float ov = __shfl_xor_sync(0xffffffffu, v, o);
        int   oi = __shfl_xor_sync(0xffffffffu, i, o);
        if (ov > v || (ov == v && oi < i)) { v = ov; i = oi; }
    }
}

__device__ __forceinline__ float warp_sum(float v) {
    #pragma unroll
    for (int o = 16; o; o >>= 1) v += __shfl_xor_sync(0xffffffffu, v, o);
    return v;
}

// ---------------- main fused kernel ----------------
__global__ void __launch_bounds__(NTHREADS)
fused_kernel(const float* __restrict__ X,
             const float* __restrict__ cb1,
             const float* __restrict__ cw2,
             const float* __restrict__ cb2,
             const float* __restrict__ sw1,
             const float* __restrict__ sb1,
             const float* __restrict__ sw2,
             const float* __restrict__ sb2,
             const float* __restrict__ dirs,
             const float* __restrict__ gamma,
             const float* __restrict__ beta,
             const float* __restrict__ oscale_p,
             float* __restrict__ out) {
    extern __shared__ char sm[];
    float* Csm  = (float*)sm;
    float* b1c  = (float*)(sm + PARAM_OFF);
    float* w2c0 = b1c + COMP_H;
    float* w2c1 = w2c0 + COMP_H;
    const uint32_t smem_u32 = (uint32_t)__cvta_generic_to_shared(sm);

    const int tid  = threadIdx.x;
    const int lane = tid & 31;
    const int wid  = tid >> 5;
    const int mw   = wid & 3;       // m16 subtile (SMSP-balanced lo-work)
    const int nw   = wid >> 2;      // 0..3, 11 n8-tiles each
    const int r0   = blockIdx.x * M_BLK;
    const bool do_lo = (nw >= 2);   // warps whose tile range reaches sig columns

    if (tid < COMP_H) {
        b1c[tid]  = cb1[tid];
        w2c0[tid] = cw2[tid * 2 + 0];
        w2c1[tid] = cw2[tid * 2 + 1];
    }
    const float oscale = oscale_p[0];
    const float b2_0 = cb2[0];
    const float b2_1 = cb2[1];

    float acc[NT_PER][4];
    #pragma unroll
    for (int t = 0; t < NT_PER; ++t)
        #pragma unroll
        for (int j = 0; j < 4; ++j) acc[t][j] = 0.f;

    const float4* X4 = (const float4*)X;

    // ---- prologue: stage chunk 0 ----
    {
        float4 av[2];
        #pragma unroll
        for (int rep = 0; rep < 2; ++rep) {
            int s = tid + rep * NTHREADS;
            av[rep] = X4[(size_t)(r0 + (s >> 4)) * (D_MODEL / 4) + (s & 15)];
        }
        // B chunk 0 -> stage 0
        const char* src = (const char*)&g_Wcat[0][0][0];
        uint32_t bb = smem_u32 + 2 * A_BYTES;
        #pragma unroll
        for (int rep = 0; rep < 6; ++rep) {
            int s = tid + rep * NTHREADS;
            if (s < (NCOL_PAD * KC * 2) / 16) {
                cp16(bb + (s >> 3) * (ASTRIDE * 2) + (s & 7) * 16, src + s * 16);
            }
        }
        asm volatile("cp.async.commit_group;\n");
        // A chunk 0 -> stage 0 (hi + lo)
        __nv_bfloat16* Ah = (__nv_bfloat16*)sm;
        __nv_bfloat16* Al = (__nv_bfloat16*)(sm + A_BYTES);
        #pragma unroll
        for (int rep = 0; rep < 2; ++rep) {
            int s = tid + rep * NTHREADS;
            int row = s >> 4, c4 = s & 15;
            float4 v = av[rep];
            __nv_bfloat162 h0 = __floats2bfloat162_rn(v.x, v.y);
            __nv_bfloat162 h1 = __floats2bfloat162_rn(v.z, v.w);
            __nv_bfloat162 l0 = __floats2bfloat162_rn(v.x - __low2float(h0), v.y - __high2float(h0));
            __nv_bfloat162 l1 = __floats2bfloat162_rn(v.z - __low2float(h1), v.w - __high2float(h1));
            *(__nv_bfloat162*)&Ah[row * ASTRIDE + c4 * 4]     = h0;
            *(__nv_bfloat162*)&Ah[row * ASTRIDE + c4 * 4 + 2] = h1;
            *(__nv_bfloat162*)&Al[row * ASTRIDE + c4 * 4]     = l0;
            *(__nv_bfloat162*)&Al[row * ASTRIDE + c4 * 4 + 2] = l1;
        }
        asm volatile("cp.async.wait_group 0;\n");
        __syncthreads();
    }

    // ---- pipelined mainloop ----
    for (int kc = 0; kc < NCHUNK; ++kc) {
        const int cur = kc & 1, nxt = cur ^ 1;
        __nv_bfloat16* Ah = (__nv_bfloat16*)(sm + cur * STAGE_BYTES);
        __nv_bfloat16* Al = (__nv_bfloat16*)(sm + cur * STAGE_BYTES + A_BYTES);
        __nv_bfloat16* Bs = (__nv_bfloat16*)(sm + cur * STAGE_BYTES + 2 * A_BYTES);
        const bool has_next = (kc + 1 < NCHUNK);

        float4 av[2];
        if (has_next) {
            #pragma unroll
            for (int rep = 0; rep < 2; ++rep) {
                int s = tid + rep * NTHREADS;
                av[rep] = X4[(size_t)(r0 + (s >> 4)) * (D_MODEL / 4) + (kc + 1) * 16 + (s & 15)];
            }
            const char* src = (const char*)&g_Wcat[kc + 1][0][0];
            uint32_t bb = smem_u32 + nxt * STAGE_BYTES + 2 * A_BYTES;
            #pragma unroll
            for (int rep = 0; rep < 6; ++rep) {
                int s = tid + rep * NTHREADS;
                if (s < (NCOL_PAD * KC * 2) / 16) {
                    cp16(bb + (s >> 3) * (ASTRIDE * 2) + (s & 7) * 16, src + s * 16);
                }
            }
        }
        asm volatile("cp.async.commit_group;\n");

        // MMAs on current stage
        #pragma unroll
        for (int ks = 0; ks < 4; ++ks) {
            const int ar = mw * 16 + (lane >> 2);
            const int ac = ks * 16 + (lane & 3) * 2;
            uint32_t a0 = *(const uint32_t*)&Ah[ar * ASTRIDE + ac];
            uint32_t a1 = *(const uint32_t*)&Ah[(ar + 8) * ASTRIDE + ac];
            uint32_t a2 = *(const uint32_t*)&Ah[ar * ASTRIDE + ac + 8];
            uint32_t a3 = *(const uint32_t*)&Ah[(ar + 8) * ASTRIDE + ac + 8];
            uint32_t l0 = 0, l1 = 0, l2 = 0, l3 = 0;
            if (do_lo) {
                l0 = *(const uint32_t*)&Al[ar * ASTRIDE + ac];
                l1 = *(const uint32_t*)&Al[(ar + 8) * ASTRIDE + ac];
                l2 = *(const uint32_t*)&Al[ar * ASTRIDE + ac + 8];
                l3 = *(const uint32_t*)&Al[(ar + 8) * ASTRIDE + ac + 8];
            }
            #pragma unroll
            for (int nt = 0; nt < NT_PER; ++nt) {
                const int g = nw * NT_PER + nt;
                const int br = g * 8 + (lane >> 2);
                uint32_t b0 = *(const uint32_t*)&Bs[br * ASTRIDE + ac];
                uint32_t b1 = *(const uint32_t*)&Bs[br * ASTRIDE + ac + 8];
                mma16816(acc[nt], a0, a1, a2, a3, b0, b1);
                if (g >= 32)  // signature columns: add x_lo correction (exact routing)
                    mma16816(acc[nt], l0, l1, l2, l3, b0, b1);
            }
        }

        if (has_next) {
            __nv_bfloat16* Ahn = (__nv_bfloat16*)(sm + nxt * STAGE_BYTES);
            __nv_bfloat16* Aln = (__nv_bfloat16*)(sm + nxt * STAGE_BYTES + A_BYTES);
            #pragma unroll
            for (int rep = 0; rep < 2; ++rep) {
                int s = tid + rep * NTHREADS;
                int row = s >> 4, c4 = s & 15;
                float4 v = av[rep];
                __nv_bfloat162 h0 = __floats2bfloat162_rn(v.x, v.y);
                __nv_bfloat162 h1 = __floats2bfloat162_rn(v.z, v.w);
                __nv_bfloat162 l0 = __floats2bfloat162_rn(v.x - __low2float(h0), v.y - __high2float(h0));
                __nv_bfloat162 l1 = __floats2bfloat162_rn(v.z - __low2float(h1), v.w - __high2float(h1));
                *(__nv_bfloat162*)&Ahn[row * ASTRIDE + c4 * 4]     = h0;
                *(__nv_bfloat162*)&Ahn[row * ASTRIDE + c4 * 4 + 2] = h1;
                *(__nv_bfloat162*)&Aln[row * ASTRIDE + c4 * 4]     = l0;
                *(__nv_bfloat162*)&Aln[row * ASTRIDE + c4 * 4 + 2] = l1;
            }
        }
        asm volatile("cp.async.wait_group 0;\n");
        __syncthreads();
    }

    // ---- dump C to smem ----
    #pragma unroll
    for (int nt = 0; nt < NT_PER; ++nt) {
        int nb = (nw * NT_PER + nt) * 8;
        int cr = mw * 16 + (lane >> 2);
        int cc = nb + (lane & 3) * 2;
        *(float2*)&Csm[cr * CSTRIDE + cc]       = make_float2(acc[nt][0], acc[nt][1]);
        *(float2*)&Csm[(cr + 8) * CSTRIDE + cc] = make_float2(acc[nt][2], acc[nt][3]);
    }
    __syncthreads();

    // ---- epilogue: one warp per token, 4 tokens per warp ----
    for (int it = 0; it < 4; ++it) {
        const int m = wid * 4 + it;
        const int r = r0 + m;
        const float* crow = Csm + m * CSTRIDE;

        float s0 = 0.f, s1 = 0.f;
        #pragma unroll
        for (int jj = 0; jj < 8; ++jj) {
            int j = lane + jj * 32;
            float h = gelu_exact(crow[j] + b1c[j]);
            s0 += h * w2c0[j];
            s1 += h * w2c1[j];
        }
        s0 = warp_sum(s0);
        s1 = warp_sum(s1);
        float comp0 = tanhf(s0 + b2_0);
        float comp1 = tanhf(s1 + b2_1);

        // routing (calibration is monotone -> argmax of raw scores)
        float cv = -INFINITY; int ci = 1 << 20;
        if (lane < NUM_CL) { cv = crow[COMP_H + lane]; ci = lane; }
        warp_argmax(cv, ci);
        float tv = -INFINITY; int tl = 1 << 20;
        if (lane < TPC) { tv = crow[COMP_H + NUM_CL + ci * TPC + lane]; tl = lane; }
        warp_argmax(tv, tl);
        const int tile = ci * TPC + tl;

        // tiny spline MLP
        float contrib = 0.f;
        if (lane < GRIDW) {
            int g = lane;
            float hw = comp0 * sw1[tile * 32 + g] + comp1 * sw1[tile * 32 + 16 + g]
                       + sb1[tile * 16 + g];
            hw = fmaxf(hw, 0.f);
            contrib = hw * sw2[tile * 16 + g];
        }
        float mag = warp_sum(contrib) + sb2[tile];
        const float factor = mag * oscale;

        // residual + layernorm (fp32 exact)
        const float* xr = X + (size_t)r * D_MODEL;
        const float* dr = dirs + (size_t)tile * D_MODEL;
        float f[32];
        float sum = 0.f, sumsq = 0.f;
        #pragma unroll
        for (int ii = 0; ii < 32; ++ii) {
            int i = lane + ii * 32;
            float y = xr[i] + factor * dr[i];
            f[ii] = y;
            sum += y;
            sumsq += y * y;
        }
        sum   = warp_sum(sum);
        sumsq = warp_sum(sumsq);
        const float mu   = sum * (1.f / D_MODEL);
        const float var  = sumsq * (1.f / D_MODEL) - mu * mu;
        const float rstd = rsqrtf(var + EPS_LN);
        float* orow = out + (size_t)r * D_MODEL;
        #pragma unroll
        for (int ii = 0; ii < 32; ++ii) {
            int i = lane + ii * 32;
            orow[i] = (f[ii] - mu) * rstd * gamma[i] + beta[i];
        }
    }
}

// ---------------- launch ----------------
extern "C" void kernel_launch(void* const* d_in, const int* in_sizes, int n_in,
                              void* d_out, int out_size) {
    const float* x      = (const float*)d_in[0];
    const float* sraw   = (const float*)d_in[1];
    // d_in[2] knot_values, d_in[3] temperature: unused (calibration monotone)
    const float* cw1    = (const float*)d_in[4];
    const float* cb1    = (const float*)d_in[5];
    const float* cw2    = (const float*)d_in[6];
    const float* cb2    = (const float*)d_in[7];
    const float* sw1    = (const float*)d_in[8];
    const float* sb1    = (const float*)d_in[9];
    const float* sw2    = (const float*)d_in[10];
    const float* sb2    = (const float*)d_in[11];
    const float* dirs   = (const float*)d_in[12];
    const float* gamma  = (const float*)d_in[13];
    const float* beta   = (const float*)d_in[14];
    const float* oscale = (const float*)d_in[15];
    float* out = (float*)d_out;

    const int N = in_sizes[0] / D_MODEL;     // 16384
    const int nblocks = N / M_BLK;           // 256

    cudaFuncSetAttribute(fused_kernel,
                         cudaFuncAttributeMaxDynamicSharedMemorySize, SMEM_TOTAL);

    prep_kernel<<<(NCOL_PAD * D_MODEL + 255) / 256, 256>>>(sraw, cw1);
    fused_kernel<<<nblocks, NTHREADS, SMEM_TOTAL>>>(
        x, cb1, cw2, cb2, sw1, sb1, sw2, sb2, dirs, gamma, beta, oscale, out);
}

// round 6
// speedup vs baseline: 1.2654x; 1.1804x over previous
#include <cuda_runtime.h>
#include <cuda_bf16.h>
#include <cstdint>
#include <math.h>

// ---------------- problem constants ----------------
#define D_MODEL   1024
#define NUM_TILES 64
#define TPC       8
#define NUM_CL    8
#define COMP_H    256
#define GRIDW     16
#define EPS_LN    1e-5f

// ---------------- GEMM config ----------------
#define NCOL_PAD  352              // 44 n8-tiles (256 hidden + 8 cluster + 64 tile + pad)
#define M_BLK     64
#define KC        64
#define NCHUNK    (D_MODEL / KC)   // 16
#define ASTRIDE   72               // elements; 144B row stride, ldmatrix conflict-free
#define ROWB      (ASTRIDE * 2)    // 144
#define CSTRIDE   (NCOL_PAD + 4)   // 356
#define NTHREADS  512
#define NT_PER    11               // n8-tiles per warp (4 n-warps)

#define A_BYTES      (M_BLK * ROWB)           // 9216
#define B_BYTES      (NCOL_PAD * ROWB)        // 50688
#define STAGE_BYTES  (A_BYTES + B_BYTES)      // 59904
#define PARAM_OFF    (2 * STAGE_BYTES)        // 119808
#define SMEM_TOTAL   (PARAM_OFF + 3 * COMP_H * 4)

// Wcat, chunk-major: [chunk][row n][k within chunk]
__device__ __nv_bfloat16 g_Wcat[NCHUNK][NCOL_PAD][KC];

// ---------------- prep: ternary sigs + cluster sigs + bf16 W1 ----------------
__global__ void prep_kernel(const float* __restrict__ raw,
                            const float* __restrict__ w1) {
    int idx = blockIdx.x * blockDim.x + threadIdx.x;
    if (idx >= NCOL_PAD * D_MODEL) return;
    int n = idx / D_MODEL;
    int k = idx % D_MODEL;
    float val;
    if (n < COMP_H) {
        val = w1[k * COMP_H + n];
    } else if (n < COMP_H + NUM_CL) {
        int c = n - COMP_H;
        float s = 0.f;
        #pragma unroll
        for (int j = 0; j < TPC; ++j) {
            float rv = raw[(c * TPC + j) * D_MODEL + k];
            s += (rv > 0.3f) ? 1.f : ((rv < -0.3f) ? -1.f : 0.f);
        }
        val = (s > 0.f) ? 1.f : ((s < 0.f) ? -1.f : 0.f);
    } else if (n < COMP_H + NUM_CL + NUM_TILES) {
        float rv = raw[(n - COMP_H - NUM_CL) * D_MODEL + k];
        val = (rv > 0.3f) ? 1.f : ((rv < -0.3f) ? -1.f : 0.f);
    } else {
        val = 0.f;
    }
    g_Wcat[k >> 6][n][k & 63] = __float2bfloat16(val);
}

// ---------------- helpers ----------------
__device__ __forceinline__ float gelu_exact(float v) {
    return 0.5f * v * (1.0f + erff(v * 0.7071067811865476f));
}
__device__ __forceinline__ void mma16816(float c[4], uint32_t a0, uint32_t a1,
                                         uint32_t a2, uint32_t a3,
                                         uint32_t b0, uint32_t b1) {
    asm volatile(
        "mma.sync.aligned.m16n8k16.row.col.f32.bf16.bf16.f32 "
        "{%0,%1,%2,%3}, {%4,%5,%6,%7}, {%8,%9}, {%0,%1,%2,%3};\n"
        : "+f"(c[0]), "+f"(c[1]), "+f"(c[2]), "+f"(c[3])
        : "r"(a0), "r"(a1), "r"(a2), "r"(a3), "r"(b0), "r"(b1));
}
__device__ __forceinline__ void ldsm_x4(uint32_t& r0, uint32_t& r1, uint32_t& r2,
                                        uint32_t& r3, uint32_t addr) {
    asm volatile("ldmatrix.sync.aligned.m8n8.x4.shared.b16 {%0,%1,%2,%3}, [%4];"
                 : "=r"(r0), "=r"(r1), "=r"(r2), "=r"(r3) : "r"(addr));
}
__device__ __forceinline__ void ldsm_x2(uint32_t& r0, uint32_t& r1, uint32_t addr) {
    asm volatile("ldmatrix.sync.aligned.m8n8.x2.shared.b16 {%0,%1}, [%2];"
                 : "=r"(r0), "=r"(r1) : "r"(addr));
}
__device__ __forceinline__ void cp16(uint32_t dst, const void* src) {
    asm volatile("cp.async.ca.shared.global [%0], [%1], 16;\n" :: "r"(dst), "l"(src));
}
__device__ __forceinline__ void warp_argmax(float& v, int& i) {
    #pragma unroll
    for (int o = 16; o; o >>= 1) {
        float ov = __shfl_xor_sync(0xffffffffu, v, o);
        int   oi = __shfl_xor_sync(0xffffffffu, i, o);
        if (ov > v || (ov == v && oi < i)) { v = ov; i = oi; }
    }
}
__device__ __forceinline__ float warp_sum(float v) {
    #pragma unroll
    for (int o = 16; o; o >>= 1) v += __shfl_xor_sync(0xffffffffu, v, o);
    return v;
}
__device__ __forceinline__ uint32_t as_u32(__nv_bfloat162 h) {
    return *reinterpret_cast<uint32_t*>(&h);
}

// ---------------- main fused kernel ----------------
__global__ void __launch_bounds__(NTHREADS)
fused_kernel(const float* __restrict__ X,
             const float* __restrict__ cb1,
             const float* __restrict__ cw2,
             const float* __restrict__ cb2,
             const float* __restrict__ sw1,
             const float* __restrict__ sb1,
             const float* __restrict__ sw2,
             const float* __restrict__ sb2,
             const float* __restrict__ dirs,
             const float* __restrict__ gamma,
             const float* __restrict__ beta,
             const float* __restrict__ oscale_p,
             float* __restrict__ out) {
    extern __shared__ char sm[];
    float* Csm  = (float*)sm;
    float* b1c  = (float*)(sm + PARAM_OFF);
    float* w2c0 = b1c + COMP_H;
    float* w2c1 = w2c0 + COMP_H;
    const uint32_t smem_u32 = (uint32_t)__cvta_generic_to_shared(sm);

    const int tid  = threadIdx.x;
    const int lane = tid & 31;
    const int wid  = tid >> 5;
    const int mw   = wid & 3;       // m16 subtile
    const int nw   = wid >> 2;      // 0..3, 11 n8-tiles each
    const int r0   = blockIdx.x * M_BLK;

    if (tid < COMP_H) {
        b1c[tid]  = cb1[tid];
        w2c0[tid] = cw2[tid * 2 + 0];
        w2c1[tid] = cw2[tid * 2 + 1];
    }
    const float oscale = oscale_p[0];
    const float b2_0 = cb2[0];
    const float b2_1 = cb2[1];

    float acc[NT_PER][4];
    #pragma unroll
    for (int t = 0; t < NT_PER; ++t)
        #pragma unroll
        for (int j = 0; j < 4; ++j) acc[t][j] = 0.f;

    const float4* X4 = (const float4*)X;

    // per-warp ldmatrix source addresses (within a stage)
    // A: lanes 0-15 -> m rows 0..15, lanes>>4 -> k-half
    const uint32_t a_lm_off = (uint32_t)((mw * 16 + (lane & 15)) * ROWB + (lane >> 4) * 16);
    // B x4 (tile pair): n row = (pair + (lane>>4&1))*8 + (lane&7), k-half = (lane>>3)&1
    const uint32_t b_lm_off4 = (uint32_t)((((lane >> 4) & 1) * 8 + (lane & 7)) * ROWB
                                          + ((lane >> 3) & 1) * 16);
    // B x2 (single tile): lanes 0-15 only; clamp upper lanes into range
    const uint32_t b_lm_off2 = (uint32_t)(((lane & 7)) * ROWB + (((lane >> 3) & 1)) * 16);

    // ---- prologue: stage 0 <- chunk 0 ----
    {
        // B
        const char* src = (const char*)&g_Wcat[0][0][0];
        uint32_t bb = smem_u32 + A_BYTES;
        #pragma unroll
        for (int rep = 0; rep < 6; ++rep) {
            int s = tid + rep * NTHREADS;
            if (s < (NCOL_PAD * KC * 2) / 16)
                cp16(bb + (s >> 3) * ROWB + (s & 7) * 16, src + s * 16);
        }
        asm volatile("cp.async.commit_group;\n");
        // A: 64 rows x 64 fp32 -> bf16, one 8-float segment per thread
        {
            int row = tid >> 3, sg = tid & 7;
            const float4* p = X4 + (size_t)(r0 + row) * (D_MODEL / 4) + sg * 2;
            float4 v0 = p[0], v1 = p[1];
            uint4 hh = make_uint4(as_u32(__floats2bfloat162_rn(v0.x, v0.y)),
                                  as_u32(__floats2bfloat162_rn(v0.z, v0.w)),
                                  as_u32(__floats2bfloat162_rn(v1.x, v1.y)),
                                  as_u32(__floats2bfloat162_rn(v1.z, v1.w)));
            *(uint4*)(sm + row * ROWB + sg * 16) = hh;
        }
        asm volatile("cp.async.wait_group 0;\n");
        __syncthreads();
    }

    // ---- pipelined mainloop ----
    for (int kc = 0; kc < NCHUNK; ++kc) {
        const int cur = kc & 1, nxt = cur ^ 1;
        const bool has_next = (kc + 1 < NCHUNK);
        const uint32_t sb = smem_u32 + cur * STAGE_BYTES;

        float4 v0, v1;
        int arow = tid >> 3, asg = tid & 7;
        if (has_next) {
            const float4* p = X4 + (size_t)(r0 + arow) * (D_MODEL / 4) + (kc + 1) * 16 + asg * 2;
            v0 = p[0]; v1 = p[1];
            const char* src = (const char*)&g_Wcat[kc + 1][0][0];
            uint32_t bb = smem_u32 + nxt * STAGE_BYTES + A_BYTES;
            #pragma unroll
            for (int rep = 0; rep < 6; ++rep) {
                int s = tid + rep * NTHREADS;
                if (s < (NCOL_PAD * KC * 2) / 16)
                    cp16(bb + (s >> 3) * ROWB + (s & 7) * 16, src + s * 16);
            }
        }
        asm volatile("cp.async.commit_group;\n");

        // MMAs on current stage via ldmatrix
        #pragma unroll
        for (int ks = 0; ks < 4; ++ks) {
            uint32_t a0, a1, a2, a3;
            ldsm_x4(a0, a1, a2, a3, sb + a_lm_off + ks * 32);
            const uint32_t bbase = sb + A_BYTES + (uint32_t)(nw * NT_PER * 8 * ROWB) + ks * 32;
            #pragma unroll
            for (int p = 0; p < 5; ++p) {
                uint32_t b0, b1, c0, c1;
                ldsm_x4(b0, b1, c0, c1, bbase + b_lm_off4 + (uint32_t)(p * 16 * ROWB));
                mma16816(acc[2 * p],     a0, a1, a2, a3, b0, b1);
                mma16816(acc[2 * p + 1], a0, a1, a2, a3, c0, c1);
            }
            {
                uint32_t b0, b1;
                ldsm_x2(b0, b1, bbase + b_lm_off2 + (uint32_t)(10 * 8 * ROWB));
                mma16816(acc[10], a0, a1, a2, a3, b0, b1);
            }
        }

        if (has_next) {
            char* abase = sm + nxt * STAGE_BYTES;
            uint4 hh = make_uint4(as_u32(__floats2bfloat162_rn(v0.x, v0.y)),
                                  as_u32(__floats2bfloat162_rn(v0.z, v0.w)),
                                  as_u32(__floats2bfloat162_rn(v1.x, v1.y)),
                                  as_u32(__floats2bfloat162_rn(v1.z, v1.w)));
            *(uint4*)(abase + arow * ROWB + asg * 16) = hh;
        }
        asm volatile("cp.async.wait_group 0;\n");
        __syncthreads();
    }

    // ---- dump C to smem ----
    #pragma unroll
    for (int nt = 0; nt < NT_PER; ++nt) {
        int nb = (nw * NT_PER + nt) * 8;
        int cr = mw * 16 + (lane >> 2);
        int cc = nb + (lane & 3) * 2;
        *(float2*)&Csm[cr * CSTRIDE + cc]       = make_float2(acc[nt][0], acc[nt][1]);
        *(float2*)&Csm[(cr + 8) * CSTRIDE + cc] = make_float2(acc[nt][2], acc[nt][3]);
    }
    __syncthreads();

    // ---- epilogue: one warp per token, 4 tokens per warp ----
    for (int it = 0; it < 4; ++it) {
        const int m = wid * 4 + it;
        const int r = r0 + m;
        const float* crow = Csm + m * CSTRIDE;

        float s0 = 0.f, s1 = 0.f;
        #pragma unroll
        for (int jj = 0; jj < 8; ++jj) {
            int j = lane + jj * 32;
            float h = gelu_exact(crow[j] + b1c[j]);
            s0 += h * w2c0[j];
            s1 += h * w2c1[j];
        }
        s0 = warp_sum(s0);
        s1 = warp_sum(s1);
        float comp0 = tanhf(s0 + b2_0);
        float comp1 = tanhf(s1 + b2_1);

        // routing (calibration monotone -> argmax of raw scores)
        float cv = -INFINITY; int ci = 1 << 20;
        if (lane < NUM_CL) { cv = crow[COMP_H + lane]; ci = lane; }
        warp_argmax(cv, ci);
        float tv = -INFINITY; int tl = 1 << 20;
        if (lane < TPC) { tv = crow[COMP_H + NUM_CL + ci * TPC + lane]; tl = lane; }
        warp_argmax(tv, tl);
        const int tile = ci * TPC + tl;

        // tiny spline MLP
        float contrib = 0.f;
        if (lane < GRIDW) {
            int g = lane;
            float hw = comp0 * sw1[tile * 32 + g] + comp1 * sw1[tile * 32 + 16 + g]
                       + sb1[tile * 16 + g];
            hw = fmaxf(hw, 0.f);
            contrib = hw * sw2[tile * 16 + g];
        }
        float mag = warp_sum(contrib) + sb2[tile];
        const float factor = mag * oscale;

        // residual + layernorm (fp32 exact)
        const float* xr = X + (size_t)r * D_MODEL;
        const float* dr = dirs + (size_t)tile * D_MODEL;
        float f[32];
        float sum = 0.f, sumsq = 0.f;
        #pragma unroll
        for (int ii = 0; ii < 32; ++ii) {
            int i = lane + ii * 32;
            float y = xr[i] + factor * dr[i];
            f[ii] = y;
            sum += y;
            sumsq += y * y;
        }
        sum   = warp_sum(sum);
        sumsq = warp_sum(sumsq);
        const float mu   = sum * (1.f / D_MODEL);
        const float var  = sumsq * (1.f / D_MODEL) - mu * mu;
        const float rstd = rsqrtf(var + EPS_LN);
        float* orow = out + (size_t)r * D_MODEL;
        #pragma unroll
        for (int ii = 0; ii < 32; ++ii) {
            int i = lane + ii * 32;
            orow[i] = (f[ii] - mu) * rstd * gamma[i] + beta[i];
        }
    }
}

// ---------------- launch ----------------
extern "C" void kernel_launch(void* const* d_in, const int* in_sizes, int n_in,
                              void* d_out, int out_size) {
    const float* x      = (const float*)d_in[0];
    const float* sraw   = (const float*)d_in[1];
    // d_in[2] knot_values, d_in[3] temperature: unused (calibration monotone)
    const float* cw1    = (const float*)d_in[4];
    const float* cb1    = (const float*)d_in[5];
    const float* cw2    = (const float*)d_in[6];
    const float* cb2    = (const float*)d_in[7];
    const float* sw1    = (const float*)d_in[8];
    const float* sb1    = (const float*)d_in[9];
    const float* sw2    = (const float*)d_in[10];
    const float* sb2    = (const float*)d_in[11];
    const float* dirs   = (const float*)d_in[12];
    const float* gamma  = (const float*)d_in[13];
    const float* beta   = (const float*)d_in[14];
    const float* oscale = (const float*)d_in[15];
    float* out = (float*)d_out;

    const int N = in_sizes[0] / D_MODEL;     // 16384
    const int nblocks = N / M_BLK;           // 256

    cudaFuncSetAttribute(fused_kernel,
                         cudaFuncAttributeMaxDynamicSharedMemorySize, SMEM_TOTAL);

    prep_kernel<<<(NCOL_PAD * D_MODEL + 255) / 256, 256>>>(sraw, cw1);
    fused_kernel<<<nblocks, NTHREADS, SMEM_TOTAL>>>(
        x, cb1, cw2, cb2, sw1, sb1, sw2, sb2, dirs, gamma, beta, oscale, out);
}